// round 5
// baseline (speedup 1.0000x reference)
#include <cuda_runtime.h>

#define BATCH 8
#define HEADS 8
#define SEQ   1024
#define DM    512
#define DH    64

// Scratch (device globals: allowed; no runtime allocation)
__device__ float g_q[BATCH*HEADS*SEQ*DH];  // [B,H,S,64]
__device__ float g_k[BATCH*HEADS*SEQ*DH];
__device__ float g_v[BATCH*HEADS*SEQ*DH];
__device__ float g_x[BATCH*SEQ*DM];        // merged-head attention output

// ---------------------------------------------------------------------------
// GEMM: out = A[M=8192,K=512] @ W[512,512] + bias, optional head-split store.
// 128x128 tile, BK=16, 256 threads, 8x8 microtile.
// ---------------------------------------------------------------------------
template<bool SPLIT>
__global__ __launch_bounds__(256) void gemm_bias_k(
    const float* __restrict__ A, const float* __restrict__ W,
    const float* __restrict__ bias, float* __restrict__ out)
{
    __shared__ float As[16][132];   // transposed: As[k][row]
    __shared__ float Bs[16][132];   // natural:    Bs[k][col]

    const int t  = threadIdx.x;
    const int tx = t & 15, ty = t >> 4;
    const int m0 = blockIdx.y * 128;
    const int n0 = blockIdx.x * 128;

    float acc[8][8];
#pragma unroll
    for (int i = 0; i < 8; i++)
#pragma unroll
        for (int j = 0; j < 8; j++) acc[i][j] = 0.f;

    for (int k0 = 0; k0 < 512; k0 += 16) {
#pragma unroll
        for (int i = 0; i < 2; i++) {           // A tile 128x16 -> transposed
            int f   = t + i * 256;
            int row = f >> 2;
            int c4  = (f & 3) << 2;
            float4 v = *(const float4*)&A[(m0 + row) * 512 + k0 + c4];
            As[c4 + 0][row] = v.x; As[c4 + 1][row] = v.y;
            As[c4 + 2][row] = v.z; As[c4 + 3][row] = v.w;
        }
#pragma unroll
        for (int i = 0; i < 2; i++) {           // B tile 16x128
            int f   = t + i * 256;
            int row = f >> 5;
            int c4  = (f & 31) << 2;
            *(float4*)&Bs[row][c4] = *(const float4*)&W[(k0 + row) * 512 + n0 + c4];
        }
        __syncthreads();
#pragma unroll
        for (int kk = 0; kk < 16; kk++) {
            float4 a0 = *(float4*)&As[kk][ty * 4];
            float4 a1 = *(float4*)&As[kk][64 + ty * 4];
            float4 b0 = *(float4*)&Bs[kk][tx * 4];
            float4 b1 = *(float4*)&Bs[kk][64 + tx * 4];
            float a[8] = {a0.x,a0.y,a0.z,a0.w,a1.x,a1.y,a1.z,a1.w};
            float b[8] = {b0.x,b0.y,b0.z,b0.w,b1.x,b1.y,b1.z,b1.w};
#pragma unroll
            for (int i = 0; i < 8; i++)
#pragma unroll
                for (int j = 0; j < 8; j++) acc[i][j] = fmaf(a[i], b[j], acc[i][j]);
        }
        __syncthreads();
    }

#pragma unroll
    for (int ih = 0; ih < 2; ih++) {
#pragma unroll
        for (int i = 0; i < 4; i++) {
            int r = m0 + ih * 64 + ty * 4 + i;
#pragma unroll
            for (int jh = 0; jh < 2; jh++) {
                int c = n0 + jh * 64 + tx * 4;
                float4 v;
                v.x = acc[ih*4+i][jh*4+0] + bias[c+0];
                v.y = acc[ih*4+i][jh*4+1] + bias[c+1];
                v.z = acc[ih*4+i][jh*4+2] + bias[c+2];
                v.w = acc[ih*4+i][jh*4+3] + bias[c+3];
                if (SPLIT) {
                    int b = r >> 10, s = r & 1023;
                    int h = c >> 6,  d = c & 63;
                    *(float4*)&out[(size_t)(((b*HEADS + h)*SEQ) + s)*DH + d] = v;
                } else {
                    *(float4*)&out[(size_t)r * DM + c] = v;
                }
            }
        }
    }
}

// ---------------------------------------------------------------------------
// Attention: per (b,h) x 64-row q-tile. Two passes over K-chunks of 64.
// Pass 1: scores = (Q K^T)/8 + mask*-1e9; online row max/sum-exp; raw scores
//         written to the attn output region (re-read from L2 in pass 2).
// Pass 2: attn = softmax * additional_weights (written out) ; O += attn @ V.
// ---------------------------------------------------------------------------
__global__ __launch_bounds__(256) void attn_k(
    const float* __restrict__ mask,   // [B,S]
    const float* __restrict__ addw,   // [B,S,S]
    float* __restrict__ attn_out)     // [B,H,S,S]
{
    __shared__ float sA[64][68];  // pass1: Q^T[d][q]   pass2: attn^T[k][q]
    __shared__ float sB[64][68];  // pass1: K^T[d][k]   pass2: V[k][d]
    __shared__ float mS[64];

    const int t  = threadIdx.x;
    const int tx = t & 15, ty = t >> 4;
    const int qt = blockIdx.x;          // q tile (0..15)
    const int bh = blockIdx.y;          // 0..63
    const int b  = bh >> 3, h = bh & 7;

    const float* Qg = g_q + (size_t)(bh*SEQ + qt*64) * DH;
    const float* Kg = g_k + (size_t)bh * SEQ * DH;
    const float* Vg = g_v + (size_t)bh * SEQ * DH;
    float* att = attn_out + (size_t)(bh*SEQ + qt*64) * SEQ;

    // Q tile -> transposed smem
#pragma unroll
    for (int i = 0; i < 4; i++) {
        int f   = t + i * 256;
        int row = f >> 4;
        int c4  = (f & 15) << 2;
        float4 v = *(const float4*)&Qg[row * DH + c4];
        sA[c4+0][row] = v.x; sA[c4+1][row] = v.y;
        sA[c4+2][row] = v.z; sA[c4+3][row] = v.w;
    }

    const int q0 = ty * 4;
    const int c0 = tx * 4;

    float m[4], l[4];
#pragma unroll
    for (int i = 0; i < 4; i++) { m[i] = -1e30f; l[i] = 0.f; }

    // ----------------- pass 1 -----------------
    for (int kt = 0; kt < 16; kt++) {
        __syncthreads();
#pragma unroll
        for (int i = 0; i < 4; i++) {    // K chunk -> transposed
            int f   = t + i * 256;
            int row = f >> 4;
            int c4  = (f & 15) << 2;
            float4 v = *(const float4*)&Kg[(kt*64 + row) * DH + c4];
            sB[c4+0][row] = v.x; sB[c4+1][row] = v.y;
            sB[c4+2][row] = v.z; sB[c4+3][row] = v.w;
        }
        if (t < 16)
            *(float4*)&mS[t*4] = *(const float4*)&mask[b*SEQ + kt*64 + t*4];
        __syncthreads();

        float acc[4][4];
#pragma unroll
        for (int i = 0; i < 4; i++)
#pragma unroll
            for (int j = 0; j < 4; j++) acc[i][j] = 0.f;

#pragma unroll
        for (int d = 0; d < 64; d++) {
            float4 a4 = *(float4*)&sA[d][q0];
            float4 b4 = *(float4*)&sB[d][c0];
            float a[4]  = {a4.x,a4.y,a4.z,a4.w};
            float bb[4] = {b4.x,b4.y,b4.z,b4.w};
#pragma unroll
            for (int i = 0; i < 4; i++)
#pragma unroll
                for (int j = 0; j < 4; j++) acc[i][j] = fmaf(a[i], bb[j], acc[i][j]);
        }

        float msk[4];
#pragma unroll
        for (int j = 0; j < 4; j++) msk[j] = mS[c0 + j] * (-1e9f);

#pragma unroll
        for (int i = 0; i < 4; i++) {
            float s0 = acc[i][0] * 0.125f + msk[0];
            float s1 = acc[i][1] * 0.125f + msk[1];
            float s2 = acc[i][2] * 0.125f + msk[2];
            float s3 = acc[i][3] * 0.125f + msk[3];

            float cm = fmaxf(fmaxf(s0, s1), fmaxf(s2, s3));
#pragma unroll
            for (int off = 8; off >= 1; off >>= 1)
                cm = fmaxf(cm, __shfl_xor_sync(0xffffffffu, cm, off));
            float ps = __expf(s0 - cm) + __expf(s1 - cm)
                     + __expf(s2 - cm) + __expf(s3 - cm);
#pragma unroll
            for (int off = 8; off >= 1; off >>= 1)
                ps += __shfl_xor_sync(0xffffffffu, ps, off);

            float nm = fmaxf(m[i], cm);
            l[i] = l[i] * __expf(m[i] - nm) + ps * __expf(cm - nm);
            m[i] = nm;

            float4 w = {s0, s1, s2, s3};
            *(float4*)&att[(size_t)(q0 + i) * SEQ + kt*64 + c0] = w;  // raw scores
        }
    }

    float inv[4];
#pragma unroll
    for (int i = 0; i < 4; i++) inv[i] = 1.0f / l[i];

    float O[4][4];
#pragma unroll
    for (int i = 0; i < 4; i++)
#pragma unroll
        for (int j = 0; j < 4; j++) O[i][j] = 0.f;

    // ----------------- pass 2 -----------------
    for (int kt = 0; kt < 16; kt++) {
        __syncthreads();
#pragma unroll
        for (int i = 0; i < 4; i++) {    // V chunk, natural layout
            int f   = t + i * 256;
            int row = f >> 4;
            int c4  = (f & 15) << 2;
            *(float4*)&sB[row][c4] = *(const float4*)&Vg[(kt*64 + row) * DH + c4];
        }
#pragma unroll
        for (int i = 0; i < 4; i++) {
            int q = q0 + i;
            float4 s4 = *(float4*)&att[(size_t)q * SEQ + kt*64 + c0];
            float4 w4 = *(const float4*)&addw[((size_t)b*SEQ + qt*64 + q) * SEQ + kt*64 + c0];
            float p0 = __expf(s4.x - m[i]) * inv[i] * w4.x;
            float p1 = __expf(s4.y - m[i]) * inv[i] * w4.y;
            float p2 = __expf(s4.z - m[i]) * inv[i] * w4.z;
            float p3 = __expf(s4.w - m[i]) * inv[i] * w4.w;
            float4 o = {p0, p1, p2, p3};
            *(float4*)&att[(size_t)q * SEQ + kt*64 + c0] = o;          // final attn
            sA[c0+0][q] = p0; sA[c0+1][q] = p1;                        // attn^T[k][q]
            sA[c0+2][q] = p2; sA[c0+3][q] = p3;
        }
        __syncthreads();

#pragma unroll
        for (int kk = 0; kk < 64; kk++) {
            float4 a4 = *(float4*)&sA[kk][q0];   // attn rows (q)
            float4 b4 = *(float4*)&sB[kk][c0];   // V cols (d)
            float a[4]  = {a4.x,a4.y,a4.z,a4.w};
            float bb[4] = {b4.x,b4.y,b4.z,b4.w};
#pragma unroll
            for (int i = 0; i < 4; i++)
#pragma unroll
                for (int j = 0; j < 4; j++) O[i][j] = fmaf(a[i], bb[j], O[i][j]);
        }
    }

    // write merged-head output
#pragma unroll
    for (int i = 0; i < 4; i++) {
        int s = qt*64 + q0 + i;
        float4 v = {O[i][0], O[i][1], O[i][2], O[i][3]};
        *(float4*)&g_x[((size_t)b*SEQ + s) * DM + h*DH + c0] = v;
    }
}

// ---------------------------------------------------------------------------
extern "C" void kernel_launch(void* const* d_in, const int* in_sizes, int n_in,
                              void* d_out, int out_size)
{
    const float* q_in = (const float*)d_in[0];
    const float* k_in = (const float*)d_in[1];
    const float* v_in = (const float*)d_in[2];
    const float* mask = (const float*)d_in[3];
    const float* addw = (const float*)d_in[4];
    const float* wq   = (const float*)d_in[5];
    const float* bq   = (const float*)d_in[6];
    const float* wk   = (const float*)d_in[7];
    const float* bk   = (const float*)d_in[8];
    const float* wv   = (const float*)d_in[9];
    const float* bv   = (const float*)d_in[10];
    const float* wo   = (const float*)d_in[11];
    const float* bo   = (const float*)d_in[12];

    float* out  = (float*)d_out;                       // [B,S,DM]
    float* attn = out + (size_t)BATCH * SEQ * DM;      // [B,H,S,S]

    float *qp, *kp, *vp, *xp;
    cudaGetSymbolAddress((void**)&qp, g_q);
    cudaGetSymbolAddress((void**)&kp, g_k);
    cudaGetSymbolAddress((void**)&vp, g_v);
    cudaGetSymbolAddress((void**)&xp, g_x);

    dim3 tb(256);
    dim3 gg(DM / 128, (BATCH * SEQ) / 128);            // (4, 64)

    gemm_bias_k<true><<<gg, tb>>>(q_in, wq, bq, qp);
    gemm_bias_k<true><<<gg, tb>>>(k_in, wk, bk, kp);
    gemm_bias_k<true><<<gg, tb>>>(v_in, wv, bv, vp);
    attn_k<<<dim3(16, BATCH * HEADS), tb>>>(mask, addw, attn);
    gemm_bias_k<false><<<gg, tb>>>(xp, wo, bo, out);
}

// round 7
// speedup vs baseline: 1.0377x; 1.0377x over previous
#include <cuda_runtime.h>

typedef unsigned long long ull;

#define BATCH 8
#define HEADS 8
#define SEQ   1024
#define DM    512
#define DH    64

// Scratch (device globals: allowed; no runtime allocation)
__device__ float g_q[BATCH*HEADS*SEQ*DH];  // [B,H,S,64]
__device__ float g_k[BATCH*HEADS*SEQ*DH];
__device__ float g_v[BATCH*HEADS*SEQ*DH];
__device__ float g_x[BATCH*SEQ*DM];        // merged-head attention output

// ---------------- packed f32x2 helpers (sm_103a FFMA2 via PTX) ----------------
__device__ __forceinline__ ull dup2(float x) {
    ull r; asm("mov.b64 %0, {%1, %1};" : "=l"(r) : "f"(x)); return r;
}
__device__ __forceinline__ void fma2(ull& d, ull a, ull b) {
    asm("fma.rn.f32x2 %0, %1, %2, %0;" : "+l"(d) : "l"(a), "l"(b));
}
__device__ __forceinline__ float2 unpk(ull v) {
    float2 f; asm("mov.b64 {%0, %1}, %2;" : "=f"(f.x), "=f"(f.y) : "l"(v)); return f;
}

// ---------------------------------------------------------------------------
// GEMM: out = A[M=8192,K=512] @ W[512,512] + bias, optional head-split store.
// 128x128 tile, BK=16, 256 threads, 8x8 microtile via FFMA2.
// ---------------------------------------------------------------------------
template<bool SPLIT>
__global__ __launch_bounds__(256) void gemm_bias_k(
    const float* __restrict__ A, const float* __restrict__ W,
    const float* __restrict__ bias, float* __restrict__ out)
{
    __shared__ float As[16][132];   // transposed: As[k][row]
    __shared__ float Bs[16][132];   // natural:    Bs[k][col]

    const int t  = threadIdx.x;
    const int tx = t & 15, ty = t >> 4;
    const int m0 = blockIdx.y * 128;
    const int n0 = blockIdx.x * 128;
    const int c0 = tx * 4;          // local col block 0
    const int c1 = 64 + tx * 4;     // local col block 1

    ull acc[8][4];
#pragma unroll
    for (int i = 0; i < 8; i++)
#pragma unroll
        for (int p = 0; p < 4; p++) acc[i][p] = 0ull;

    for (int k0 = 0; k0 < 512; k0 += 16) {
#pragma unroll
        for (int i = 0; i < 2; i++) {           // A tile 128x16 -> transposed
            int f   = t + i * 256;
            int row = f >> 2;
            int c4  = (f & 3) << 2;
            float4 v = *(const float4*)&A[(size_t)(m0 + row) * 512 + k0 + c4];
            As[c4 + 0][row] = v.x; As[c4 + 1][row] = v.y;
            As[c4 + 2][row] = v.z; As[c4 + 3][row] = v.w;
        }
#pragma unroll
        for (int i = 0; i < 2; i++) {           // B tile 16x128
            int f   = t + i * 256;
            int row = f >> 5;
            int c4  = (f & 31) << 2;
            *(float4*)&Bs[row][c4] = *(const float4*)&W[(size_t)(k0 + row) * 512 + n0 + c4];
        }
        __syncthreads();
#pragma unroll
        for (int kk = 0; kk < 16; kk++) {
            float4 a0 = *(float4*)&As[kk][ty * 4];
            float4 a1 = *(float4*)&As[kk][64 + ty * 4];
            ulonglong2 B0 = *(ulonglong2*)&Bs[kk][c0];
            ulonglong2 B1 = *(ulonglong2*)&Bs[kk][c1];
            float a[8] = {a0.x, a0.y, a0.z, a0.w, a1.x, a1.y, a1.z, a1.w};
#pragma unroll
            for (int i = 0; i < 8; i++) {
                ull ad = dup2(a[i]);
                fma2(acc[i][0], ad, B0.x);
                fma2(acc[i][1], ad, B0.y);
                fma2(acc[i][2], ad, B1.x);
                fma2(acc[i][3], ad, B1.y);
            }
        }
        __syncthreads();
    }

    float bv[8];
#pragma unroll
    for (int j = 0; j < 4; j++) {
        bv[j]     = bias[n0 + c0 + j];
        bv[4 + j] = bias[n0 + c1 + j];
    }

#pragma unroll
    for (int i = 0; i < 8; i++) {
        int r = m0 + ((i < 4) ? (ty * 4 + i) : (64 + ty * 4 + i - 4));
        float2 u0 = unpk(acc[i][0]), u1 = unpk(acc[i][1]);
        float2 u2 = unpk(acc[i][2]), u3 = unpk(acc[i][3]);
        float4 v0 = {u0.x + bv[0], u0.y + bv[1], u1.x + bv[2], u1.y + bv[3]};
        float4 v1 = {u2.x + bv[4], u2.y + bv[5], u3.x + bv[6], u3.y + bv[7]};
        int ca = n0 + c0, cb = n0 + c1;
        if (SPLIT) {
            int b = r >> 10, s = r & 1023;
            int ha = ca >> 6, da = ca & 63;
            int hb = cb >> 6, db = cb & 63;
            *(float4*)&out[((size_t)((b * HEADS + ha) * SEQ) + s) * DH + da] = v0;
            *(float4*)&out[((size_t)((b * HEADS + hb) * SEQ) + s) * DH + db] = v1;
        } else {
            *(float4*)&out[(size_t)r * DM + ca] = v0;
            *(float4*)&out[(size_t)r * DM + cb] = v1;
        }
    }
}

// ---------------------------------------------------------------------------
// Attention: per (b,h) x 64-row q-tile. Two passes over K-chunks of 64.
// Pass 1: scores = (Q K^T)/8 + mask*-1e9 (FFMA2 inner); per-thread online
//         (m,l) over the thread's own 4 columns; raw scores written to the
//         attn output region. One cross-lane merge at end of pass 1.
// Pass 2: attn = softmax * additional_weights (written out); O += attn @ V
//         (FFMA2 inner).
// ---------------------------------------------------------------------------
__global__ __launch_bounds__(256) void attn_k(
    const float* __restrict__ mask,   // [B,S]
    const float* __restrict__ addw,   // [B,S,S]
    float* __restrict__ attn_out)     // [B,H,S,S]
{
    __shared__ float sA[64][68];  // pass1: Q^T[d][q]   pass2: attn^T[k][q]
    __shared__ float sB[64][68];  // pass1: K^T[d][k]   pass2: V[k][d]
    __shared__ float mS[64];

    const int t  = threadIdx.x;
    const int tx = t & 15, ty = t >> 4;
    const int qt = blockIdx.x;          // q tile (0..15)
    const int bh = blockIdx.y;          // 0..63
    const int b  = bh >> 3, h = bh & 7;

    const float* Qg = g_q + (size_t)(bh*SEQ + qt*64) * DH;
    const float* Kg = g_k + (size_t)bh * SEQ * DH;
    const float* Vg = g_v + (size_t)bh * SEQ * DH;
    float* att = attn_out + (size_t)(bh*SEQ + qt*64) * SEQ;

    // Q tile -> transposed smem
#pragma unroll
    for (int i = 0; i < 4; i++) {
        int f   = t + i * 256;
        int row = f >> 4;
        int c4  = (f & 15) << 2;
        float4 v = *(const float4*)&Qg[row * DH + c4];
        sA[c4+0][row] = v.x; sA[c4+1][row] = v.y;
        sA[c4+2][row] = v.z; sA[c4+3][row] = v.w;
    }

    const int q0 = ty * 4;
    const int c0 = tx * 4;

    float m[4], l[4];
#pragma unroll
    for (int i = 0; i < 4; i++) { m[i] = -1e30f; l[i] = 0.f; }

    // ----------------- pass 1 -----------------
    for (int kt = 0; kt < 16; kt++) {
        __syncthreads();
#pragma unroll
        for (int i = 0; i < 4; i++) {    // K chunk -> transposed
            int f   = t + i * 256;
            int row = f >> 4;
            int c4  = (f & 15) << 2;
            float4 v = *(const float4*)&Kg[(kt*64 + row) * DH + c4];
            sB[c4+0][row] = v.x; sB[c4+1][row] = v.y;
            sB[c4+2][row] = v.z; sB[c4+3][row] = v.w;
        }
        if (t < 16)
            *(float4*)&mS[t*4] = *(const float4*)&mask[b*SEQ + kt*64 + t*4];
        __syncthreads();

        ull acc[4][2];
#pragma unroll
        for (int i = 0; i < 4; i++) { acc[i][0] = 0ull; acc[i][1] = 0ull; }

#pragma unroll
        for (int d = 0; d < 64; d++) {
            float4 a4 = *(float4*)&sA[d][q0];
            ulonglong2 b2 = *(ulonglong2*)&sB[d][c0];
            ull a0 = dup2(a4.x), a1 = dup2(a4.y), a2 = dup2(a4.z), a3 = dup2(a4.w);
            fma2(acc[0][0], a0, b2.x); fma2(acc[0][1], a0, b2.y);
            fma2(acc[1][0], a1, b2.x); fma2(acc[1][1], a1, b2.y);
            fma2(acc[2][0], a2, b2.x); fma2(acc[2][1], a2, b2.y);
            fma2(acc[3][0], a3, b2.x); fma2(acc[3][1], a3, b2.y);
        }

        float msk[4];
#pragma unroll
        for (int j = 0; j < 4; j++) msk[j] = mS[c0 + j] * (-1e9f);

#pragma unroll
        for (int i = 0; i < 4; i++) {
            float2 p0 = unpk(acc[i][0]);
            float2 p1 = unpk(acc[i][1]);
            float s0 = p0.x * 0.125f + msk[0];
            float s1 = p0.y * 0.125f + msk[1];
            float s2 = p1.x * 0.125f + msk[2];
            float s3 = p1.y * 0.125f + msk[3];

            // per-thread online (m,l) over this thread's 4 columns only
            float cm = fmaxf(fmaxf(s0, s1), fmaxf(s2, s3));
            float nm = fmaxf(m[i], cm);
            l[i] = l[i] * __expf(m[i] - nm)
                 + __expf(s0 - nm) + __expf(s1 - nm)
                 + __expf(s2 - nm) + __expf(s3 - nm);
            m[i] = nm;

            float4 w = {s0, s1, s2, s3};
            *(float4*)&att[(size_t)(q0 + i) * SEQ + kt*64 + c0] = w;  // raw scores
        }
    }

    // one-time cross-lane merge over the 16 threads sharing each q row
    float inv[4];
#pragma unroll
    for (int i = 0; i < 4; i++) {
#pragma unroll
        for (int off = 1; off <= 8; off <<= 1) {
            float om = __shfl_xor_sync(0xffffffffu, m[i], off);
            float ol = __shfl_xor_sync(0xffffffffu, l[i], off);
            float nm = fmaxf(m[i], om);
            l[i] = l[i] * __expf(m[i] - nm) + ol * __expf(om - nm);
            m[i] = nm;
        }
        inv[i] = 1.0f / l[i];
    }

    ull O[4][2];
#pragma unroll
    for (int i = 0; i < 4; i++) { O[i][0] = 0ull; O[i][1] = 0ull; }

    // ----------------- pass 2 -----------------
    for (int kt = 0; kt < 16; kt++) {
        __syncthreads();
#pragma unroll
        for (int i = 0; i < 4; i++) {    // V chunk, natural layout
            int f   = t + i * 256;
            int row = f >> 4;
            int c4  = (f & 15) << 2;
            *(float4*)&sB[row][c4] = *(const float4*)&Vg[(kt*64 + row) * DH + c4];
        }
#pragma unroll
        for (int i = 0; i < 4; i++) {
            int q = q0 + i;
            float4 s4 = *(float4*)&att[(size_t)q * SEQ + kt*64 + c0];
            float4 w4 = *(const float4*)&addw[((size_t)b*SEQ + qt*64 + q) * SEQ + kt*64 + c0];
            float p0 = __expf(s4.x - m[i]) * inv[i] * w4.x;
            float p1 = __expf(s4.y - m[i]) * inv[i] * w4.y;
            float p2 = __expf(s4.z - m[i]) * inv[i] * w4.z;
            float p3 = __expf(s4.w - m[i]) * inv[i] * w4.w;
            float4 o = {p0, p1, p2, p3};
            *(float4*)&att[(size_t)q * SEQ + kt*64 + c0] = o;          // final attn
            sA[c0+0][q] = p0; sA[c0+1][q] = p1;                        // attn^T[k][q]
            sA[c0+2][q] = p2; sA[c0+3][q] = p3;
        }
        __syncthreads();

#pragma unroll
        for (int kk = 0; kk < 64; kk++) {
            float4 a4 = *(float4*)&sA[kk][q0];       // attn rows (q)
            ulonglong2 b2 = *(ulonglong2*)&sB[kk][c0]; // V cols (d), packed pairs
            ull a0 = dup2(a4.x), a1 = dup2(a4.y), a2 = dup2(a4.z), a3 = dup2(a4.w);
            fma2(O[0][0], a0, b2.x); fma2(O[0][1], a0, b2.y);
            fma2(O[1][0], a1, b2.x); fma2(O[1][1], a1, b2.y);
            fma2(O[2][0], a2, b2.x); fma2(O[2][1], a2, b2.y);
            fma2(O[3][0], a3, b2.x); fma2(O[3][1], a3, b2.y);
        }
    }

    // write merged-head output
#pragma unroll
    for (int i = 0; i < 4; i++) {
        int s = qt*64 + q0 + i;
        float2 u0 = unpk(O[i][0]);
        float2 u1 = unpk(O[i][1]);
        float4 v = {u0.x, u0.y, u1.x, u1.y};
        *(float4*)&g_x[((size_t)b*SEQ + s) * DM + h*DH + c0] = v;
    }
}

// ---------------------------------------------------------------------------
extern "C" void kernel_launch(void* const* d_in, const int* in_sizes, int n_in,
                              void* d_out, int out_size)
{
    const float* q_in = (const float*)d_in[0];
    const float* k_in = (const float*)d_in[1];
    const float* v_in = (const float*)d_in[2];
    const float* mask = (const float*)d_in[3];
    const float* addw = (const float*)d_in[4];
    const float* wq   = (const float*)d_in[5];
    const float* bq   = (const float*)d_in[6];
    const float* wk   = (const float*)d_in[7];
    const float* bk   = (const float*)d_in[8];
    const float* wv   = (const float*)d_in[9];
    const float* bv   = (const float*)d_in[10];
    const float* wo   = (const float*)d_in[11];
    const float* bo   = (const float*)d_in[12];

    float* out  = (float*)d_out;                       // [B,S,DM]
    float* attn = out + (size_t)BATCH * SEQ * DM;      // [B,H,S,S]

    float *qp, *kp, *vp, *xp;
    cudaGetSymbolAddress((void**)&qp, g_q);
    cudaGetSymbolAddress((void**)&kp, g_k);
    cudaGetSymbolAddress((void**)&vp, g_v);
    cudaGetSymbolAddress((void**)&xp, g_x);

    dim3 tb(256);
    dim3 gg(DM / 128, (BATCH * SEQ) / 128);            // (4, 64)

    gemm_bias_k<true><<<gg, tb>>>(q_in, wq, bq, qp);
    gemm_bias_k<true><<<gg, tb>>>(k_in, wk, bk, kp);
    gemm_bias_k<true><<<gg, tb>>>(v_in, wv, bv, vp);
    attn_k<<<dim3(16, BATCH * HEADS), tb>>>(mask, addw, attn);
    gemm_bias_k<false><<<gg, tb>>>(xp, wo, bo, out);
}